// round 3
// baseline (speedup 1.0000x reference)
#include <cuda_runtime.h>

#define TLEN  1024
#define BATCH 64
#define NTH   256          // 8 warps = 2 per SMSP
#define RPT   4            // rows per thread (NTH * RPT == TLEN)
#define INFV  1e30f

// Per-batch path losses + completion ticket (no allocs allowed).
__device__ float g_losses[BATCH];
__device__ unsigned int g_done = 0;   // self-resetting via atomicInc wrap

__device__ __forceinline__ float sqrt_approx(float x) {
    float r;
    asm("sqrt.approx.f32 %0, %1;" : "=f"(r) : "f"(x));
    return r;
}

// One block per batch. Thread t owns rows [t*RPT, t*RPT+RPT). Column wavefront:
// at step s, thread t processes column c = s - t for its RPT rows in registers.
// Cross-thread dep is only the bottom row of thread t-1 (double-buffered smem,
// 1 barrier/step). Two DP values carried:
//   C[i,j] = D(i,j) + min(C[i-1,j-1], C[i-1,j], C[i,j-1])
//   L[i,j] = L1w(i,j) + L[parent(i,j)]
// parent = first-min argmin in order (diag, up, left) == reference backtrace,
// so loss_b = L[T-1,T-1] with no backtrace pass.
__global__ void __launch_bounds__(NTH, 1)
dtw_loss_kernel(const float* __restrict__ preds,
                const float* __restrict__ targs,
                const float* __restrict__ subcoef,
                float* __restrict__ out)
{
    __shared__ float2 qs[TLEN];        // target (x, y) per column
    __shared__ float2 bnd[2][NTH];     // (C, L) bottom-row boundary, dbl-buffered

    const int b = blockIdx.x;
    const int t = threadIdx.x;
    const float* P = preds + (size_t)b * TLEN * 4;
    const float* Q = targs + (size_t)b * TLEN * 4;

    for (int c = t; c < TLEN; c += NTH)
        qs[c] = make_float2(Q[c * 4 + 0], Q[c * 4 + 1]);

    float pxr[RPT], pyr[RPT];
    const int rb = t * RPT;
#pragma unroll
    for (int r = 0; r < RPT; r++) {
        pxr[r] = P[(rb + r) * 4 + 0];
        pyr[r] = P[(rb + r) * 4 + 1];
    }
    const float sc0 = subcoef[0];
    const float sc1 = subcoef[1];

    float Cl[RPT], Ll[RPT];            // left-column state (column c-1)
#pragma unroll
    for (int r = 0; r < RPT; r++) { Cl[r] = INFV; Ll[r] = 0.0f; }

    float bCp = INFV, bLp = 0.0f;      // boundary diag lag (column c-1)

    __syncthreads();

    const int NSTEP = TLEN + NTH - 1;
#pragma unroll 2
    for (int s = 0; s < NSTEP; s++) {
        const int c = s - t;
        if (c >= 0 && c < TLEN) {
            const float2 qc = qs[c];

            float bC, bL;
            if (t > 0) {
                float2 v = bnd[s & 1][t - 1];   // thread t-1 bottom row, column c
                bC = v.x; bL = v.y;
            } else {
                bC = INFV; bL = 0.0f;
            }

            const bool origin = ((t | c) == 0);
            float up = bC, upL = bL, dg = bCp, dgL = bLp;

#pragma unroll
            for (int r = 0; r < RPT; r++) {
                const float dx = pxr[r] - qc.x;
                const float dy = pyr[r] - qc.y;
                const float s2 = fmaf(dx, dx, dy * dy);
                const float D  = sqrt_approx(s2);

                const float lf = Cl[r], lfL = Ll[r];
                // 3-way min, tie order (diag, up, left) == reference argmin
                const float m1  = fminf(dg, up);
                const float m1L = (dg <= up) ? dgL : upL;
                float m  = fminf(m1, lf);
                float Lp = (m1 <= lf) ? m1L : lfL;
                if (r == 0 && origin) { m = 0.0f; Lp = 0.0f; }  // C[0,0] = D[0,0]

                const float Cv = D + m;
                const float l1 = fmaf(fabsf(dy), sc1, fabsf(dx) * sc0);
                const float Lv = l1 + Lp;

                dg = lf; dgL = lfL;
                up = Cv; upL = Lv;
                Cl[r] = Cv; Ll[r] = Lv;
            }

            bCp = bC; bLp = bL;
            bnd[(s + 1) & 1][t] = make_float2(Cl[RPT - 1], Ll[RPT - 1]);

            if (t == NTH - 1 && c == TLEN - 1)
                g_losses[b] = Ll[RPT - 1];
        }
        __syncthreads();
    }

    // Last block to finish sums all batch losses in fixed order (deterministic).
    if (t == NTH - 1) {
        __threadfence();
        unsigned int old = atomicInc(&g_done, BATCH - 1);  // wraps to 0 -> self-reset
        if (old == BATCH - 1) {
            __threadfence();
            float sum = 0.0f;
#pragma unroll
            for (int k = 0; k < BATCH; k++) sum += g_losses[k];
            out[0] = sum;
        }
    }
}

extern "C" void kernel_launch(void* const* d_in, const int* in_sizes, int n_in,
                              void* d_out, int out_size)
{
    const float* preds   = (const float*)d_in[0];
    const float* targs   = (const float*)d_in[1];
    const float* subcoef = (const float*)d_in[2];
    float* out = (float*)d_out;
    (void)in_sizes; (void)n_in; (void)out_size;

    dtw_loss_kernel<<<BATCH, NTH>>>(preds, targs, subcoef, out);
}

// round 5
// speedup vs baseline: 1.2139x; 1.2139x over previous
#include <cuda_runtime.h>

#define TLEN  1024
#define BATCH 64
#define NTH   256              // 8 warps = 2 per SMSP
#define RPT   4                // rows per thread (NTH*RPT == TLEN)
#define NPAIR 512              // column pairs (2 cols per step)
#define NSTEP (NPAIR + NTH - 1)
#define INFV  1e30f

__device__ float g_losses[BATCH];
__device__ unsigned int g_done = 0;    // self-resetting ticket

__device__ __forceinline__ float sqrt_approx(float x) {
    float r; asm("sqrt.approx.f32 %0, %1;" : "=f"(r) : "f"(x)); return r;
}

// One block per batch. Thread t owns rows 4t..4t+3. At step s it processes
// column pair k = s - t (cols 2k, 2k+1): an 8-cell 4x2 tile entirely in
// registers. Cross-thread dep: bottom row of thread t-1 at this pair,
// double-buffered in shared (one float4: C,L at c0 and c1). DP carried:
//   C[i,j] = D(i,j) + min(diag, up, left)
//   L[i,j] = L1w(i,j) + L[parent], parent = first-min in order (diag, up,
// left) == reference backtrace rule, so loss = L[T-1,T-1], no backtrace.
__global__ void __launch_bounds__(NTH, 1)
dtw_kernel(const float* __restrict__ preds, const float* __restrict__ targs,
           const float* __restrict__ subcoef, float* __restrict__ out)
{
    __shared__ float4 qs[NPAIR];          // (qx0,qy0,qx1,qy1) per pair
    __shared__ float4 bnd[2][NTH + 1];    // bottom-row boundary, ghost slot 0

    const int b = blockIdx.x;
    const int t = threadIdx.x;
    const float* P = preds + (size_t)b * TLEN * 4;
    const float* Q = targs + (size_t)b * TLEN * 4;

    for (int k = t; k < NPAIR; k += NTH) {
        float4 a = *(const float4*)(Q + 8 * k);
        float4 c = *(const float4*)(Q + 8 * k + 4);
        qs[k] = make_float4(a.x, a.y, c.x, c.y);
    }
    float px[RPT], py[RPT];
    const int rb = t * RPT;
#pragma unroll
    for (int r = 0; r < RPT; r++) {
        px[r] = P[(rb + r) * 4 + 0];
        py[r] = P[(rb + r) * 4 + 1];
    }
    const float sc0 = subcoef[0], sc1 = subcoef[1];

    if (t == 0) {                          // constant top boundary for thread 0
        float4 inf4 = make_float4(INFV, 0.f, INFV, 0.f);
        bnd[0][0] = inf4; bnd[1][0] = inf4;
    }

    float Cl[RPT], Ll[RPT];                // own rows at col c-1
#pragma unroll
    for (int r = 0; r < RPT; r++) { Cl[r] = INFV; Ll[r] = 0.f; }
    float bCp = INFV, bLp = 0.f;           // t-1 bottom at col c0-1 (diag lag)

    __syncthreads();

    for (int s = 0; s < NSTEP; ++s) {
        const int k  = s - t;
        const int Pw = s & 1;
        if (k >= 0 && k < NPAIR) {
            const float4 bv = bnd[Pw ^ 1][t];   // t-1 bottom at {c0, c1}
            const float4 q  = qs[k];

            float A[RPT], LA[RPT];          // column c0 results
            {
                float dg = bCp, dgL = bLp, up = bv.x, upL = bv.y;
#pragma unroll
                for (int r = 0; r < RPT; r++) {
                    const float dx = px[r] - q.x, dy = py[r] - q.y;
                    const float D  = sqrt_approx(fmaf(dx, dx, dy * dy));
                    const float m1  = fminf(dg, up);
                    const float m1L = (dg <= up) ? dgL : upL;
                    float m  = fminf(m1, Cl[r]);
                    float Lp = (m1 <= Cl[r]) ? m1L : Ll[r];
                    if (r == 0 && t == 0 && k == 0) { m = 0.f; Lp = 0.f; } // origin
                    A[r]  = D + m;
                    LA[r] = fmaf(fabsf(dy), sc1, fabsf(dx) * sc0) + Lp;
                    dg = Cl[r]; dgL = Ll[r];    // diag for next row
                    up = A[r];  upL = LA[r];    // up   for next row
                }
            }
            float Bv[RPT], LB[RPT];         // column c1 results
            {
                float dg = bv.x, dgL = bv.y, up = bv.z, upL = bv.w;
#pragma unroll
                for (int r = 0; r < RPT; r++) {
                    const float dx = px[r] - q.z, dy = py[r] - q.w;
                    const float D  = sqrt_approx(fmaf(dx, dx, dy * dy));
                    const float m1  = fminf(dg, up);
                    const float m1L = (dg <= up) ? dgL : upL;
                    const float m  = fminf(m1, A[r]);
                    const float Lp = (m1 <= A[r]) ? m1L : LA[r];
                    Bv[r] = D + m;
                    LB[r] = fmaf(fabsf(dy), sc1, fabsf(dx) * sc0) + Lp;
                    dg = A[r];  dgL = LA[r];
                    up = Bv[r]; upL = LB[r];
                }
            }
#pragma unroll
            for (int r = 0; r < RPT; r++) { Cl[r] = Bv[r]; Ll[r] = LB[r]; }
            bCp = bv.z; bLp = bv.w;

            bnd[Pw][t + 1] = make_float4(A[RPT-1], LA[RPT-1], Bv[RPT-1], LB[RPT-1]);

            if (t == NTH - 1 && k == NPAIR - 1)   // cell (1023,1023)
                g_losses[b] = LB[RPT-1];
        }
        __syncthreads();
    }

    // Last block sums all batch losses in fixed order (deterministic).
    if (t == NTH - 1) {
        __threadfence();
        unsigned int old = atomicInc(&g_done, BATCH - 1);  // wraps -> self-reset
        if (old == BATCH - 1) {
            __threadfence();
            float sum = 0.f;
#pragma unroll
            for (int i = 0; i < BATCH; i++) sum += __ldcg(&g_losses[i]);
            out[0] = sum;
        }
    }
}

extern "C" void kernel_launch(void* const* d_in, const int* in_sizes, int n_in,
                              void* d_out, int out_size)
{
    const float* preds   = (const float*)d_in[0];
    const float* targs   = (const float*)d_in[1];
    const float* subcoef = (const float*)d_in[2];
    float* out = (float*)d_out;
    (void)in_sizes; (void)n_in; (void)out_size;

    dtw_kernel<<<BATCH, NTH>>>(preds, targs, subcoef, out);
}